// round 3
// baseline (speedup 1.0000x reference)
#include <cuda_runtime.h>

// ---------------------------------------------------------------------------
// MPS_RNN_2D forward.  L=M=8, S=2, D=32.  B from in_sizes[0]/64.
// Inputs (metadata order): x[B,64] i32, M_h[8,8,2,32,32] f32, M_v same,
// v[8,8,2,32] f32, w[8,8,32] f32, c[8,8] f32, eta[8,8,32] f32.
// Output: [B,2] f32 (log|psi|, phase).
// ---------------------------------------------------------------------------

#define DD   32
#define NQ   64
#define EPSF 1e-10f

#define TPB   256
#define WARPS 8
#define WELE  4                 // batch elements per warp
#define EPB   (WARPS * WELE)    // 32 elements per block

// Repacked parameters (scan order): per site a [32(b)][32(d)] array of
// float4 {Mh[s=0][d][b], Mh[s=1][d][b], Mv[s=0][d][b], Mv[s=1][d][b]}.
__device__ float4 g_packed[64 * 1024];
// Per-site vectors: [site][0]=v(s=0), [1]=v(s=1), [2]=eta^2, [3]=w
__device__ float  g_vec[64][4][DD];
__device__ float  g_c[64];

// ---------------------------------------------------------------------------
__global__ void repack_kernel(const float* __restrict__ Mh,
                              const float* __restrict__ Mv,
                              const float* __restrict__ v,
                              const float* __restrict__ w,
                              const float* __restrict__ c,
                              const float* __restrict__ eta) {
    int site = blockIdx.x;            // 0..63 in scan order
    int row  = site >> 3;
    int j    = site & 7;
    int col  = (row & 1) ? (7 - j) : j;   // snake: lattice column
    int cell = row * 8 + col;

    int t = threadIdx.x;              // 1024 threads: one (b,d) each
    int b = t >> 5;
    int d = t & 31;

    const float* mh = Mh + (size_t)cell * 2048;   // [s][d][b]
    const float* mv = Mv + (size_t)cell * 2048;
    float4 p;
    p.x = mh[        d * 32 + b];
    p.y = mh[1024 +  d * 32 + b];
    p.z = mv[        d * 32 + b];
    p.w = mv[1024 +  d * 32 + b];
    g_packed[site * 1024 + b * 32 + d] = p;

    if (t < DD) {
        g_vec[site][0][t] = v[cell * 64 + t];
        g_vec[site][1][t] = v[cell * 64 + 32 + t];
        float e = eta[cell * 32 + t];
        g_vec[site][2][t] = e * e;
        g_vec[site][3][t] = w[cell * 32 + t];
        if (t == 0) g_c[site] = c[cell];
    }
}

// ---------------------------------------------------------------------------
__device__ __forceinline__ float f4get(const float4& v, int q) {
    return q == 0 ? v.x : (q == 1 ? v.y : (q == 2 ? v.z : v.w));
}

// One site for WELE elements of this warp.  FIRST = row 0 (vertical input
// is the zero boundary -> skip those loads and FMAs entirely).
template <bool FIRST>
__device__ __forceinline__ void site_compute(
    const float4* __restrict__ sM,   // [b][d] staged matrices
    float* __restrict__ sHL,         // [EPB][32]  left hidden
    float* __restrict__ sHV,         // [EPB][8][32] lattice hidden
    int lane, int ebl, int col,
    float rv0, float rv1, float re2, float rw, float rc,
    const unsigned* xm, int site, float* la, int* ncnt)
{
    float hc0a[WELE], hc0b[WELE], hc1a[WELE], hc1b[WELE];
    #pragma unroll
    for (int k = 0; k < WELE; k++) {
        hc0a[k] = rv0; hc0b[k] = 0.0f;
        hc1a[k] = rv1; hc1b[k] = 0.0f;
    }

    #pragma unroll
    for (int bb = 0; bb < 32; bb += 4) {
        float4 hl[WELE], hv[WELE];
        #pragma unroll
        for (int k = 0; k < WELE; k++) {
            hl[k] = *reinterpret_cast<const float4*>(&sHL[(ebl + k) * DD + bb]);
            if (!FIRST)
                hv[k] = *reinterpret_cast<const float4*>(
                    &sHV[((ebl + k) * 8 + col) * DD + bb]);
        }
        #pragma unroll
        for (int q = 0; q < 4; q++) {
            float4 m = sM[(bb + q) * DD + lane];
            #pragma unroll
            for (int k = 0; k < WELE; k++) {
                float l_ = f4get(hl[k], q);
                hc0a[k] = fmaf(m.x, l_, hc0a[k]);
                hc1a[k] = fmaf(m.y, l_, hc1a[k]);
                if (!FIRST) {
                    float v_ = f4get(hv[k], q);
                    hc0b[k] = fmaf(m.z, v_, hc0b[k]);
                    hc1b[k] = fmaf(m.w, v_, hc1b[k]);
                }
            }
        }
    }

    // epilogue per element
    #pragma unroll
    for (int k = 0; k < WELE; k++) {
        float hc0 = hc0a[k] + hc0b[k];
        float hc1 = hc1a[k] + hc1b[k];
        unsigned m32 = (site < 32) ? xm[2 * k] : xm[2 * k + 1];
        int s = (int)((m32 >> (site & 31)) & 1u);
        float hsel = s ? hc1 : hc0;
        float hoth = s ? hc0 : hc1;

        float qsel = re2 * hsel * hsel;   // p[selected] contribution
        float qoth = re2 * hoth * hoth;   // p[other]
        float nrm  = hsel * hsel;
        float aw   = hsel * rw;
        #pragma unroll
        for (int off = 16; off; off >>= 1) {
            qsel += __shfl_xor_sync(0xffffffffu, qsel, off);
            qoth += __shfl_xor_sync(0xffffffffu, qoth, off);
            nrm  += __shfl_xor_sync(0xffffffffu, nrm,  off);
            aw   += __shfl_xor_sync(0xffffffffu, aw,   off);
        }
        float ptot = qsel + qoth;
        la[k] += 0.5f * (__logf(qsel + EPSF) - __logf(ptot + EPSF));
        float inv = 1.0f / (sqrtf(nrm) + EPSF);
        float hn  = hsel * inv;
        float a   = aw * inv + rc;
        ncnt[k] += (a < 0.0f) ? 1 : 0;

        sHL[(ebl + k) * DD + lane] = hn;
        sHV[((ebl + k) * 8 + col) * DD + lane] = hn;
    }
}

// ---------------------------------------------------------------------------
__global__ void __launch_bounds__(TPB)
mps_main_kernel(const int* __restrict__ x, float* __restrict__ out, int B)
{
    extern __shared__ float smem[];
    float4* sM  = reinterpret_cast<float4*>(smem);        // 1024 float4
    float*  sHL = smem + 4096;                            // [EPB][32]
    float*  sHV = smem + 4096 + EPB * DD;                 // [EPB][8][32]

    const int lane = threadIdx.x & 31;
    const int wid  = threadIdx.x >> 5;
    const int ebl  = wid * WELE;
    const long eg0 = (long)blockIdx.x * EPB + ebl;

    // Pack x rows into bitmasks (bit i of lo/hi = occupation at site i / 32+i)
    unsigned xm[2 * WELE];
    #pragma unroll
    for (int k = 0; k < WELE; k++) {
        long e = eg0 + k;
        int v0 = 0, v1 = 0;
        if (e < B) {
            v0 = x[e * NQ + lane];
            v1 = x[e * NQ + 32 + lane];
        }
        xm[2 * k]     = __ballot_sync(0xffffffffu, v0 != 0);
        xm[2 * k + 1] = __ballot_sync(0xffffffffu, v1 != 0);
    }

    float la[WELE];
    int   ncnt[WELE];
    #pragma unroll
    for (int k = 0; k < WELE; k++) { la[k] = 0.0f; ncnt[k] = 0; }

    for (int row = 0; row < 8; ++row) {
        // left boundary = ones at start of each row
        #pragma unroll
        for (int k = 0; k < WELE; k++) sHL[(ebl + k) * DD + lane] = 1.0f;

        #pragma unroll 1
        for (int j = 0; j < 8; ++j) {
            int site = row * 8 + j;
            int col  = (row & 1) ? (7 - j) : j;

            float rv0 = g_vec[site][0][lane];
            float rv1 = g_vec[site][1][lane];
            float re2 = g_vec[site][2][lane];
            float rw  = g_vec[site][3][lane];
            float rc  = g_c[site];

            __syncthreads();   // protect sM (also orders sHL/sHV writes)
            {
                const float4* gp = g_packed + site * 1024;
                #pragma unroll
                for (int t = threadIdx.x; t < 1024; t += TPB) sM[t] = gp[t];
            }
            __syncthreads();

            if (row == 0)
                site_compute<true >(sM, sHL, sHV, lane, ebl, col,
                                    rv0, rv1, re2, rw, rc, xm, site, la, ncnt);
            else
                site_compute<false>(sM, sHL, sHV, lane, ebl, col,
                                    rv0, rv1, re2, rw, rc, xm, site, la, ncnt);
        }
    }

    #pragma unroll
    for (int k = 0; k < WELE; k++) {
        long e = eg0 + k;
        if (lane == 0 && e < B) {
            out[e * 2 + 0] = la[k];
            out[e * 2 + 1] = 3.14159274101257324f * (float)ncnt[k];
        }
    }
}

// ---------------------------------------------------------------------------
extern "C" void kernel_launch(void* const* d_in, const int* in_sizes, int n_in,
                              void* d_out, int out_size) {
    const int*   x   = (const int*)  d_in[0];
    const float* Mh  = (const float*)d_in[1];
    const float* Mv  = (const float*)d_in[2];
    const float* v   = (const float*)d_in[3];
    const float* w   = (const float*)d_in[4];
    const float* c   = (const float*)d_in[5];
    const float* eta = (const float*)d_in[6];
    float* out = (float*)d_out;

    int B = in_sizes[0] / NQ;

    repack_kernel<<<64, 1024>>>(Mh, Mv, v, w, c, eta);

    const size_t smem_bytes = (size_t)(4096 + EPB * DD + EPB * 8 * DD) * sizeof(float);
    cudaFuncSetAttribute(mps_main_kernel,
                         cudaFuncAttributeMaxDynamicSharedMemorySize,
                         (int)smem_bytes);

    int grid = (B + EPB - 1) / EPB;
    mps_main_kernel<<<grid, TPB, smem_bytes>>>(x, out, B);
}

// round 4
// speedup vs baseline: 1.2740x; 1.2740x over previous
#include <cuda_runtime.h>

// ---------------------------------------------------------------------------
// MPS_RNN_2D forward.  L=M=8, S=2, D=32.
// Inputs: x[B,64] i32, M_h[8,8,2,32,32] f32, M_v same, v[8,8,2,32] f32,
// w[8,8,32] f32, c[8,8] f32, eta[8,8,32] f32.  Output [B,2] f32.
//
// Design: lane = bond index d.  WELE=8 batch elements per warp.  Hidden
// states live in warp-private shared memory (no block barriers at all).
// Matrices are repacked once per launch into [site][b4][comp][d] float4
// (4 consecutive b values per load) and read via LDG (L1-resident, 16KB/site).
// Inner product uses fma.rn.f32x2: each FFMA2 does 2 b-contraction steps,
// halving FMA-pipe issue vs scalar FFMA with zero packing overhead.
// ---------------------------------------------------------------------------

#define NQ    64
#define EPSF  1e-10f
#define TPB   128
#define WELE  8
#define EPB   32            // (TPB/32) * WELE

// [site][b4(8)][comp(4)][d(32)] float4 over b: comp 0=Mh(s0),1=Mh(s1),2=Mv(s0),3=Mv(s1)
__device__ float4 g2[64 * 1024];          // 1 MB
__device__ float4 g_vecp[64 * 32];        // [site][d] = {v0, v1, eta^2, w}
__device__ float  g_c[64];

#define FFMA2(acc, m, h) \
    asm("fma.rn.f32x2 %0, %1, %2, %0;" : "+l"(acc) : "l"(m), "l"(h))
#define UNPACK2(lo, hi, p) \
    asm("mov.b64 {%0, %1}, %2;" : "=f"(lo), "=f"(hi) : "l"(p))

// ---------------------------------------------------------------------------
__global__ void repack_kernel(const float* __restrict__ Mh,
                              const float* __restrict__ Mv,
                              const float* __restrict__ v,
                              const float* __restrict__ w,
                              const float* __restrict__ c,
                              const float* __restrict__ eta) {
    int site = blockIdx.x;                // scan order
    int row  = site >> 3;
    int j    = site & 7;
    int col  = (row & 1) ? (7 - j) : j;   // snake
    int cell = row * 8 + col;

    int t    = threadIdx.x;               // 1024 threads
    int d    = t & 31;
    int idx  = t >> 5;                    // 0..31
    int comp = idx & 3;
    int b4   = idx >> 2;                  // 0..7

    const float* base = (comp < 2) ? Mh : Mv;
    const float* src  = base + (size_t)cell * 2048 + (size_t)(comp & 1) * 1024
                        + d * 32 + b4 * 4;
    g2[site * 1024 + (b4 * 4 + comp) * 32 + d] = *(const float4*)src;

    if (t < 32) {
        float e = eta[cell * 32 + t];
        float4 gv;
        gv.x = v[cell * 64 + t];
        gv.y = v[cell * 64 + 32 + t];
        gv.z = e * e;
        gv.w = w[cell * 32 + t];
        g_vecp[site * 32 + t] = gv;
        if (t == 0) g_c[site] = c[cell];
    }
}

// ---------------------------------------------------------------------------
// matvec accumulation for one site, WELE elements.  acc0/acc1 hold f32x2
// partial sums (even-b lane, odd-b lane) for occupation 0 / 1.
template <bool FIRST>
__device__ __forceinline__ void site_matvec(
    const ulonglong2* __restrict__ gm,     // site matrices
    const float* __restrict__ sHLw,        // [WELE][32]
    const float* __restrict__ sHVw,        // [WELE][8][32]
    int col,
    unsigned long long* acc0, unsigned long long* acc1, int lane)
{
    #pragma unroll
    for (int b4 = 0; b4 < 8; ++b4) {
        const ulonglong2* gb = gm + (b4 * 4) * 32 + lane;
        ulonglong2 m0 = gb[0];         // Mh s0, b..b+3
        ulonglong2 m1 = gb[32];        // Mh s1
        ulonglong2 m2, m3;
        if (!FIRST) { m2 = gb[64]; m3 = gb[96]; }   // Mv s0/s1

        #pragma unroll
        for (int k = 0; k < WELE; ++k) {
            ulonglong2 hl = *reinterpret_cast<const ulonglong2*>(
                sHLw + k * 32 + b4 * 4);
            FFMA2(acc0[k], m0.x, hl.x);  FFMA2(acc0[k], m0.y, hl.y);
            FFMA2(acc1[k], m1.x, hl.x);  FFMA2(acc1[k], m1.y, hl.y);
            if (!FIRST) {
                ulonglong2 hv = *reinterpret_cast<const ulonglong2*>(
                    sHVw + (k * 8 + col) * 32 + b4 * 4);
                FFMA2(acc0[k], m2.x, hv.x);  FFMA2(acc0[k], m2.y, hv.y);
                FFMA2(acc1[k], m3.x, hv.x);  FFMA2(acc1[k], m3.y, hv.y);
            }
        }
    }
}

// ---------------------------------------------------------------------------
__global__ void __launch_bounds__(TPB, 4)
mps_main_kernel(const int* __restrict__ x, float* __restrict__ out, int B)
{
    extern __shared__ float smem[];
    float* sHL = smem;                     // [EPB][32]
    float* sHV = smem + EPB * 32;          // [EPB][8][32]

    const int lane = threadIdx.x & 31;
    const int wid  = threadIdx.x >> 5;
    const int ebl  = wid * WELE;
    float* sHLw = sHL + ebl * 32;
    float* sHVw = sHV + ebl * 8 * 32;
    const long eg0 = (long)blockIdx.x * EPB + ebl;

    // occupation bitmasks: xm[2k] = sites 0..31, xm[2k+1] = sites 32..63
    unsigned xm[2 * WELE];
    #pragma unroll
    for (int k = 0; k < WELE; ++k) {
        long e = eg0 + k;
        int v0 = 0, v1 = 0;
        if (e < B) {
            v0 = x[e * NQ + lane];
            v1 = x[e * NQ + 32 + lane];
        }
        xm[2 * k]     = __ballot_sync(0xffffffffu, v0 != 0);
        xm[2 * k + 1] = __ballot_sync(0xffffffffu, v1 != 0);
    }

    float la[WELE];
    int   ncnt[WELE];
    #pragma unroll
    for (int k = 0; k < WELE; ++k) { la[k] = 0.0f; ncnt[k] = 0; }

    #pragma unroll 1
    for (int row = 0; row < 8; ++row) {
        #pragma unroll
        for (int k = 0; k < WELE; ++k) sHLw[k * 32 + lane] = 1.0f;  // left bc
        __syncwarp();

        #pragma unroll 1
        for (int j = 0; j < 8; ++j) {
            const int site = row * 8 + j;
            const int col  = (row & 1) ? (7 - j) : j;

            const float4 gv = g_vecp[site * 32 + lane];   // {v0,v1,eta2,w}
            const float  rc = g_c[site];
            const ulonglong2* gm =
                reinterpret_cast<const ulonglong2*>(g2) + site * 1024;

            unsigned long long acc0[WELE], acc1[WELE];
            #pragma unroll
            for (int k = 0; k < WELE; ++k) { acc0[k] = 0ull; acc1[k] = 0ull; }

            if (row == 0)
                site_matvec<true >(gm, sHLw, sHVw, col, acc0, acc1, lane);
            else
                site_matvec<false>(gm, sHLw, sHVw, col, acc0, acc1, lane);

            #pragma unroll
            for (int k = 0; k < WELE; ++k) {
                float e0, o0, e1, o1;
                UNPACK2(e0, o0, acc0[k]);
                UNPACK2(e1, o1, acc1[k]);
                float hc0 = e0 + o0 + gv.x;
                float hc1 = e1 + o1 + gv.y;

                unsigned m32 = (site < 32) ? xm[2 * k] : xm[2 * k + 1];
                int s = (int)((m32 >> (site & 31)) & 1u);
                float hsel = s ? hc1 : hc0;
                float hoth = s ? hc0 : hc1;

                float qs = gv.z * hsel * hsel;
                float qo = gv.z * hoth * hoth;
                float nr = hsel * hsel;
                float aw = gv.w * hsel;
                #pragma unroll
                for (int off = 16; off; off >>= 1) {
                    qs += __shfl_xor_sync(0xffffffffu, qs, off);
                    qo += __shfl_xor_sync(0xffffffffu, qo, off);
                    nr += __shfl_xor_sync(0xffffffffu, nr, off);
                    aw += __shfl_xor_sync(0xffffffffu, aw, off);
                }
                la[k] += 0.5f * (__logf(qs + EPSF) - __logf(qs + qo + EPSF));
                float inv = __fdividef(1.0f, sqrtf(nr) + EPSF);
                float hn  = hsel * inv;
                ncnt[k]  += ((aw * inv + rc) < 0.0f) ? 1 : 0;

                sHLw[k * 32 + lane]              = hn;
                sHVw[(k * 8 + col) * 32 + lane]  = hn;
            }
            __syncwarp();
        }
    }

    if (lane == 0) {
        #pragma unroll
        for (int k = 0; k < WELE; ++k) {
            long e = eg0 + k;
            if (e < B) {
                out[e * 2 + 0] = la[k];
                out[e * 2 + 1] = 3.14159274101257324f * (float)ncnt[k];
            }
        }
    }
}

// ---------------------------------------------------------------------------
extern "C" void kernel_launch(void* const* d_in, const int* in_sizes, int n_in,
                              void* d_out, int out_size) {
    const int*   x   = (const int*)  d_in[0];
    const float* Mh  = (const float*)d_in[1];
    const float* Mv  = (const float*)d_in[2];
    const float* v   = (const float*)d_in[3];
    const float* w   = (const float*)d_in[4];
    const float* c   = (const float*)d_in[5];
    const float* eta = (const float*)d_in[6];
    float* out = (float*)d_out;

    int B = in_sizes[0] / NQ;

    repack_kernel<<<64, 1024>>>(Mh, Mv, v, w, c, eta);

    const size_t smem_bytes = (size_t)(EPB * 32 + EPB * 8 * 32) * sizeof(float);
    cudaFuncSetAttribute(mps_main_kernel,
                         cudaFuncAttributeMaxDynamicSharedMemorySize,
                         (int)smem_bytes);

    int grid = (B + EPB - 1) / EPB;
    mps_main_kernel<<<grid, TPB, smem_bytes>>>(x, out, B);
}